// round 4
// baseline (speedup 1.0000x reference)
#include <cuda_runtime.h>
#include <cuda_fp16.h>
#include <cstdint>
#include <cstddef>

#define MDIM 16384
#define NDIM 4096
#define KDIM 2048
#define HDIM 1024

#define BM 256
#define BN 128
#define BK 32
#define STAGES 4
#define THREADS 256
#define NKT (KDIM / BK)              // 64

#define A_BYTES 16384                // 16 mblk x 2 ks x 512B
#define B_BYTES 8192                 // 16 nblk x 512B
#define STAGE_BYTES (A_BYTES + B_BYTES)   // 24576

// Fragment-packed operands (device globals: allowed scratch)
__device__ __half g_Apack[(size_t)MDIM * KDIM];   // 64 MB
__device__ __half g_Wpack[(size_t)NDIM * KDIM];   // 16 MB

// ---------------- helpers ----------------
__device__ __forceinline__ uint32_t cvta_s(const void* p) {
    return (uint32_t)__cvta_generic_to_shared(p);
}
__device__ __forceinline__ void cp_async16(uint32_t s, const void* g) {
    asm volatile("cp.async.cg.shared.global [%0], [%1], 16;\n" :: "r"(s), "l"(g));
}
__device__ __forceinline__ void cp_commit() { asm volatile("cp.async.commit_group;\n" ::: "memory"); }
#define CP_WAIT(n) asm volatile("cp.async.wait_group %0;\n" :: "n"(n) : "memory")

__device__ __forceinline__ void mma_f16(float* d, const uint32_t* a, const uint32_t* b) {
    asm volatile("mma.sync.aligned.m16n8k16.row.col.f32.f16.f16.f32 "
        "{%0,%1,%2,%3}, {%4,%5,%6,%7}, {%8,%9}, {%0,%1,%2,%3};\n"
        : "+f"(d[0]), "+f"(d[1]), "+f"(d[2]), "+f"(d[3])
        : "r"(a[0]), "r"(a[1]), "r"(a[2]), "r"(a[3]), "r"(b[0]), "r"(b[1]));
}

// ---------------- pack kernels (verified round 3) ----------------
__global__ void pack_A(const float* __restrict__ inc, const float* __restrict__ oh) {
    int idx = blockIdx.x * blockDim.x + threadIdx.x;     // one 16B chunk
    int lane = idx & 31;
    int unit = idx >> 5;
    int kblk = unit & 127;        // K/16
    int mblk = unit >> 7;
    int gid = lane >> 2, q = lane & 3;
    int m0 = mblk * 16 + gid;
    int k0 = kblk * 16 + 2 * q;
    const float* src;
    if (k0 < 1024) src = inc + (size_t)m0 * 1024 + k0;
    else           src = oh  + (size_t)m0 * 1024 + (k0 - 1024);
    float2 v0 = *(const float2*)(src);
    float2 v1 = *(const float2*)(src + 8 * 1024);
    float2 v2 = *(const float2*)(src + 8);
    float2 v3 = *(const float2*)(src + 8 * 1024 + 8);
    __half2 h[4];
    h[0] = __floats2half2_rn(v0.x, v0.y);
    h[1] = __floats2half2_rn(v1.x, v1.y);
    h[2] = __floats2half2_rn(v2.x, v2.y);
    h[3] = __floats2half2_rn(v3.x, v3.y);
    *(float4*)(g_Apack + (size_t)unit * 256 + lane * 8) = *(float4*)h;
}

__global__ void pack_W(const float* __restrict__ Wi, const float* __restrict__ Wh) {
    int idx = blockIdx.x * blockDim.x + threadIdx.x;
    int lane = idx & 31;
    int unit = idx >> 5;
    int kblk = unit & 63;         // K/32
    int nblk = unit >> 6;
    int gid = lane >> 2, q = lane & 3;
    int n = nblk * 8 + gid;
    int g = n & 3, hh = n >> 2;
    int k0 = kblk * 32 + 2 * q;
    const float* src;
    if (k0 < 1024) src = Wi + ((size_t)g * 1024 + hh) * 1024 + k0;
    else           src = Wh + ((size_t)g * 1024 + hh) * 1024 + (k0 - 1024);
    float2 v0 = *(const float2*)(src);
    float2 v1 = *(const float2*)(src + 8);
    float2 v2 = *(const float2*)(src + 16);
    float2 v3 = *(const float2*)(src + 24);
    __half2 h[4];
    h[0] = __floats2half2_rn(v0.x, v0.y);
    h[1] = __floats2half2_rn(v1.x, v1.y);
    h[2] = __floats2half2_rn(v2.x, v2.y);
    h[3] = __floats2half2_rn(v3.x, v3.y);
    *(float4*)(g_Wpack + (size_t)unit * 256 + lane * 8) = *(float4*)h;
}

// ---------------- main GEMM + fused LSTM epilogue ----------------
// 8 warps, warp tile 64x64: warp grid 4(M) x 2(N)
__global__ void __launch_bounds__(THREADS, 1)
lstm_mma(const float* __restrict__ old_c, const float* __restrict__ bi,
         float* __restrict__ out, long long out_size)
{
    extern __shared__ char dsm[];
    __shared__ float s_bias[BN];

    const int tid  = threadIdx.x;
    const int lane = tid & 31;
    const int warp = tid >> 5;            // 0..7
    const int wr = warp >> 1;             // 0..3 -> M (64 rows each)
    const int wc = warp & 1;              // 0..1 -> N (64 cols each)
    const int bm = blockIdx.y * BM;
    const int bn = blockIdx.x * BN;
    const int gid = lane >> 2, q = lane & 3;

    const uint32_t smem = cvta_s(dsm);

    float acc[4][8][4];
#pragma unroll
    for (int a = 0; a < 4; a++)
#pragma unroll
        for (int b = 0; b < 8; b++)
#pragma unroll
            for (int c = 0; c < 4; c++) acc[a][b][c] = 0.f;

    // producer bases: warp handles 4 A units + 2 B units per ktile
    const size_t a_row_unit = (size_t)(bm / 16) * 128;   // unit stride per mblk = 128 kblks
    const size_t b_row_unit = (size_t)(bn / 8) * 64;

    auto produce = [&](int kt, int st) {
        uint32_t sa = smem + st * STAGE_BYTES;
        uint32_t sb = sa + A_BYTES;
#pragma unroll
        for (int i = 0; i < 4; i++) {
            int u = warp * 4 + i;              // 0..31: mblk = u>>1, ks = u&1
            const __half* src = g_Apack +
                (a_row_unit + (size_t)(u >> 1) * 128 + kt * 2 + (u & 1)) * 256 + lane * 8;
            cp_async16(sa + u * 512 + lane * 16, src);
        }
#pragma unroll
        for (int i = 0; i < 2; i++) {
            int u = warp * 2 + i;              // 0..15: nblk
            const __half* src = g_Wpack + (b_row_unit + (size_t)u * 64 + kt) * 256 + lane * 8;
            cp_async16(sb + u * 512 + lane * 16, src);
        }
    };

    // prologue: stages 0..2
#pragma unroll
    for (int s = 0; s < STAGES - 1; s++) {
        produce(s, s);
        cp_commit();
    }

    for (int kt = 0; kt < NKT; kt++) {
        CP_WAIT(STAGES - 2);          // group kt complete
        __syncthreads();              // all warps done reading stage (kt-1)%4

        int nk = kt + STAGES - 1;
        if (nk < NKT) produce(nk, nk & (STAGES - 1));
        cp_commit();                  // commit every iter so wait-group math stays fixed

        const char* sA = dsm + (kt & (STAGES - 1)) * STAGE_BYTES;
        const char* sB = sA + A_BYTES;

        // B: 8 n-blocks, each 512B unit holds both k-slices
        uint32_t bfr[8][4];
#pragma unroll
        for (int nt = 0; nt < 8; nt++)
            *(uint4*)bfr[nt] = *(const uint4*)(sB + (wc * 8 + nt) * 512 + lane * 16);

#pragma unroll
        for (int ks = 0; ks < 2; ks++) {
            uint32_t afr[4][4];
#pragma unroll
            for (int mt = 0; mt < 4; mt++)
                *(uint4*)afr[mt] = *(const uint4*)(sA + ((wr * 4 + mt) * 2 + ks) * 512 + lane * 16);
#pragma unroll
            for (int mt = 0; mt < 4; mt++)
#pragma unroll
                for (int nt = 0; nt < 8; nt++)
                    mma_f16(acc[mt][nt], afr[mt], &bfr[nt][ks * 2]);
        }
    }

    // stage bias for this CTA's 128 columns (gate-interleaved source)
    __syncthreads();
    if (tid < BN) {
        int n = bn + tid;
        s_bias[tid] = bi[(n & 3) * HDIM + (n >> 2)];
    }
    __syncthreads();

    // ---- fused LSTM epilogue ----
    // acc regs: [0]=(row gid, col 2q) [1]=(row gid, col 2q+1) [2]=(+8, 2q) [3]=(+8, 2q+1)
    // even-q lane holds (i,f) pre-acts, odd-q lane (g,o) of the SAME h -> shfl.xor 1
    const long long BH = (long long)MDIM * HDIM;
    const bool seg1 = out_size >= 2 * BH;
    const bool seg2 = out_size >= 3 * BH;

#pragma unroll
    for (int mt = 0; mt < 4; mt++) {
#pragma unroll
        for (int rr = 0; rr < 2; rr++) {
            int b = bm + wr * 64 + mt * 16 + gid + rr * 8;
#pragma unroll
            for (int nt = 0; nt < 8; nt++) {
                int cn = wc * 64 + nt * 8 + 2 * q;   // local even col
                int n  = bn + cn;
                int h  = n >> 2;
                float v0 = acc[mt][nt][rr * 2 + 0] + s_bias[cn];
                float v1 = acc[mt][nt][rr * 2 + 1] + s_bias[cn + 1];
                float p0 = __shfl_xor_sync(0xffffffffu, v0, 1);
                float p1 = __shfl_xor_sync(0xffffffffu, v1, 1);
                float ipre, fpre, gpre, opre;
                if ((q & 1) == 0) { ipre = v0; fpre = v1; gpre = p0; opre = p1; }
                else              { ipre = p0; fpre = p1; gpre = v0; opre = v1; }

                float iv = 1.f / (1.f + __expf(-ipre));
                float fv = 1.f / (1.f + __expf(-fpre));
                float gv = 2.f / (1.f + __expf(-2.f * gpre)) - 1.f;
                float ov = 1.f / (1.f + __expf(-opre));

                float oc = old_c[(size_t)b * HDIM + h];
                float nc = fv * oc + iv * gv;
                float nh = ov * (2.f / (1.f + __expf(-2.f * nc)) - 1.f);

                size_t idx = (size_t)b * HDIM + h;
                if ((q & 1) == 0) {
                    out[idx] = nh;
                } else {
                    if (seg1) out[(size_t)BH + idx] = nh;
                    if (seg2) out[(size_t)(2 * BH) + idx] = nc;
                }
            }
        }
    }
}

extern "C" void kernel_launch(void* const* d_in, const int* in_sizes, int n_in,
                              void* d_out, int out_size) {
    const float* incoming = (const float*)d_in[0];
    const float* old_h    = (const float*)d_in[1];
    const float* old_c    = (const float*)d_in[2];
    const float* Wi       = (const float*)d_in[3];
    const float* bi       = (const float*)d_in[4];
    const float* Wh       = (const float*)d_in[5];
    float* out = (float*)d_out;

    int a_chunks = (MDIM / 16) * (KDIM / 16) * 32;   // 4,194,304
    int w_chunks = (NDIM / 8) * (KDIM / 32) * 32;    // 1,048,576
    pack_A<<<a_chunks / 256, 256>>>(incoming, old_h);
    pack_W<<<w_chunks / 256, 256>>>(Wi, Wh);

    static int smem_set = 0;
    if (!smem_set) {
        cudaFuncSetAttribute(lstm_mma, cudaFuncAttributeMaxDynamicSharedMemorySize,
                             STAGES * STAGE_BYTES);
        smem_set = 1;
    }
    dim3 grid(NDIM / BN, MDIM / BM);   // (32, 64)
    lstm_mma<<<grid, THREADS, STAGES * STAGE_BYTES>>>(old_c, bi, out, (long long)out_size);
}

// round 5
// speedup vs baseline: 1.5687x; 1.5687x over previous
#include <cuda_runtime.h>
#include <cuda_fp16.h>
#include <cstdint>
#include <cstddef>

#define MDIM 16384
#define NDIM 4096
#define KDIM 2048
#define HDIM 1024

#define BM 256
#define BN 128
#define BK 64
#define STAGES 3
#define THREADS 512
#define NKT (KDIM / BK)              // 32

#define A_BYTES 32768                // 16 mblk x 4 k16 x 512B
#define B_BYTES 16384                // 16 nblk x 2 k32 x 512B
#define STAGE_BYTES (A_BYTES + B_BYTES)   // 49152

// Fragment-packed operands (device globals: allowed scratch)
__device__ __half g_Apack[(size_t)MDIM * KDIM];   // 64 MB
__device__ __half g_Wpack[(size_t)NDIM * KDIM];   // 16 MB

// ---------------- helpers ----------------
__device__ __forceinline__ uint32_t cvta_s(const void* p) {
    return (uint32_t)__cvta_generic_to_shared(p);
}
__device__ __forceinline__ void cp_async16(uint32_t s, const void* g) {
    asm volatile("cp.async.cg.shared.global [%0], [%1], 16;\n" :: "r"(s), "l"(g));
}
__device__ __forceinline__ void cp_commit() { asm volatile("cp.async.commit_group;\n" ::: "memory"); }
#define CP_WAIT(n) asm volatile("cp.async.wait_group %0;\n" :: "n"(n) : "memory")

__device__ __forceinline__ void mma_f16(float* d, const uint32_t* a, const uint32_t* b) {
    asm volatile("mma.sync.aligned.m16n8k16.row.col.f32.f16.f16.f32 "
        "{%0,%1,%2,%3}, {%4,%5,%6,%7}, {%8,%9}, {%0,%1,%2,%3};\n"
        : "+f"(d[0]), "+f"(d[1]), "+f"(d[2]), "+f"(d[3])
        : "r"(a[0]), "r"(a[1]), "r"(a[2]), "r"(a[3]), "r"(b[0]), "r"(b[1]));
}
__device__ __forceinline__ float tanh_fast(float x) {
    float r; asm("tanh.approx.f32 %0, %1;\n" : "=f"(r) : "f"(x)); return r;
}
__device__ __forceinline__ float sigmoid_fast(float x) {
    return fmaf(tanh_fast(0.5f * x), 0.5f, 0.5f);
}

// ---------------- pack kernels (verified round 3) ----------------
__global__ void pack_A(const float* __restrict__ inc, const float* __restrict__ oh) {
    int idx = blockIdx.x * blockDim.x + threadIdx.x;     // one 16B chunk
    int lane = idx & 31;
    int unit = idx >> 5;
    int kblk = unit & 127;        // K/16
    int mblk = unit >> 7;
    int gid = lane >> 2, q = lane & 3;
    int m0 = mblk * 16 + gid;
    int k0 = kblk * 16 + 2 * q;
    const float* src;
    if (k0 < 1024) src = inc + (size_t)m0 * 1024 + k0;
    else           src = oh  + (size_t)m0 * 1024 + (k0 - 1024);
    float2 v0 = *(const float2*)(src);
    float2 v1 = *(const float2*)(src + 8 * 1024);
    float2 v2 = *(const float2*)(src + 8);
    float2 v3 = *(const float2*)(src + 8 * 1024 + 8);
    __half2 h[4];
    h[0] = __floats2half2_rn(v0.x, v0.y);
    h[1] = __floats2half2_rn(v1.x, v1.y);
    h[2] = __floats2half2_rn(v2.x, v2.y);
    h[3] = __floats2half2_rn(v3.x, v3.y);
    *(float4*)(g_Apack + (size_t)unit * 256 + lane * 8) = *(float4*)h;
}

__global__ void pack_W(const float* __restrict__ Wi, const float* __restrict__ Wh) {
    int idx = blockIdx.x * blockDim.x + threadIdx.x;
    int lane = idx & 31;
    int unit = idx >> 5;
    int kblk = unit & 63;         // K/32
    int nblk = unit >> 6;
    int gid = lane >> 2, q = lane & 3;
    int n = nblk * 8 + gid;
    int g = n & 3, hh = n >> 2;
    int k0 = kblk * 32 + 2 * q;
    const float* src;
    if (k0 < 1024) src = Wi + ((size_t)g * 1024 + hh) * 1024 + k0;
    else           src = Wh + ((size_t)g * 1024 + hh) * 1024 + (k0 - 1024);
    float2 v0 = *(const float2*)(src);
    float2 v1 = *(const float2*)(src + 8);
    float2 v2 = *(const float2*)(src + 16);
    float2 v3 = *(const float2*)(src + 24);
    __half2 h[4];
    h[0] = __floats2half2_rn(v0.x, v0.y);
    h[1] = __floats2half2_rn(v1.x, v1.y);
    h[2] = __floats2half2_rn(v2.x, v2.y);
    h[3] = __floats2half2_rn(v3.x, v3.y);
    *(float4*)(g_Wpack + (size_t)unit * 256 + lane * 8) = *(float4*)h;
}

// ---------------- main GEMM + fused LSTM epilogue ----------------
// 16 warps, warp tile 64x32: warp grid 4(M) x 4(N)
__global__ void __launch_bounds__(THREADS, 1)
lstm_mma(const float* __restrict__ old_c, const float* __restrict__ bi,
         float* __restrict__ out, long long out_size)
{
    extern __shared__ char dsm[];
    __shared__ float s_bias[BN];

    const int tid  = threadIdx.x;
    const int lane = tid & 31;
    const int warp = tid >> 5;            // 0..15
    const int wr = warp >> 2;             // 0..3 -> M (64 rows each)
    const int wc = warp & 3;              // 0..3 -> N (32 cols each)
    const int bm = blockIdx.y * BM;
    const int bn = blockIdx.x * BN;
    const int gid = lane >> 2, q = lane & 3;

    const uint32_t smem = cvta_s(dsm);

    // bias staged up-front (ordered by first mainloop __syncthreads)
    if (tid < BN) {
        int n = bn + tid;
        s_bias[tid] = bi[(n & 3) * HDIM + (n >> 2)];
    }

    float acc[4][4][4];
#pragma unroll
    for (int a = 0; a < 4; a++)
#pragma unroll
        for (int b = 0; b < 4; b++)
#pragma unroll
            for (int c = 0; c < 4; c++) acc[a][b][c] = 0.f;

    const size_t a_row_unit = (size_t)(bm / 16) * 128;
    const size_t b_row_unit = (size_t)(bn / 8) * 64;

    auto produce = [&](int kt, int st) {
        uint32_t sa = smem + st * STAGE_BYTES;
        uint32_t sb = sa + A_BYTES;
#pragma unroll
        for (int i = 0; i < 4; i++) {
            int u = warp * 4 + i;              // 0..63: mblk = u>>2, ks16 = u&3
            const __half* src = g_Apack +
                (a_row_unit + (size_t)(u >> 2) * 128 + kt * 4 + (u & 3)) * 256 + lane * 8;
            cp_async16(sa + u * 512 + lane * 16, src);
        }
#pragma unroll
        for (int i = 0; i < 2; i++) {
            int u = warp * 2 + i;              // 0..31: nblk = u>>1, k32 = u&1
            const __half* src = g_Wpack +
                (b_row_unit + (size_t)(u >> 1) * 64 + kt * 2 + (u & 1)) * 256 + lane * 8;
            cp_async16(sb + u * 512 + lane * 16, src);
        }
    };

    // prologue: stages 0,1
    produce(0, 0); cp_commit();
    produce(1, 1); cp_commit();

    int st = 0;           // consume stage
    int pst = 2;          // produce stage
    for (int kt = 0; kt < NKT; kt++) {
        CP_WAIT(1);                   // group kt complete
        __syncthreads();              // all warps done reading stage pst (reused now)

        int nk = kt + STAGES - 1;
        if (nk < NKT) produce(nk, pst);
        cp_commit();                  // commit every iter -> wait-group math fixed

        const char* sA = dsm + st * STAGE_BYTES;
        const char* sB = sA + A_BYTES;

#pragma unroll
        for (int ks32 = 0; ks32 < 2; ks32++) {
            uint32_t bfr[4][4];
#pragma unroll
            for (int nt = 0; nt < 4; nt++)
                *(uint4*)bfr[nt] = *(const uint4*)(sB + ((wc * 4 + nt) * 2 + ks32) * 512 + lane * 16);
#pragma unroll
            for (int ki = 0; ki < 2; ki++) {
                int ks16 = ks32 * 2 + ki;
                uint32_t afr[4][4];
#pragma unroll
                for (int mt = 0; mt < 4; mt++)
                    *(uint4*)afr[mt] = *(const uint4*)(sA + ((wr * 4 + mt) * 4 + ks16) * 512 + lane * 16);
#pragma unroll
                for (int mt = 0; mt < 4; mt++)
#pragma unroll
                    for (int nt = 0; nt < 4; nt++)
                        mma_f16(acc[mt][nt], afr[mt], &bfr[nt][ki * 2]);
            }
        }
        if (++st == STAGES) st = 0;
        if (++pst == STAGES) pst = 0;
    }

    // ---- fused LSTM epilogue (shuffle-paired, tanh.approx) ----
    const long long BH = (long long)MDIM * HDIM;
    const bool seg1 = out_size >= 2 * BH;
    const bool seg2 = out_size >= 3 * BH;

#pragma unroll
    for (int mt = 0; mt < 4; mt++) {
#pragma unroll
        for (int rr = 0; rr < 2; rr++) {
            int b = bm + wr * 64 + mt * 16 + gid + rr * 8;
#pragma unroll
            for (int nt = 0; nt < 4; nt++) {
                int cn = wc * 32 + nt * 8 + 2 * q;   // local even col
                int n  = bn + cn;
                int h  = n >> 2;
                float v0 = acc[mt][nt][rr * 2 + 0] + s_bias[cn];
                float v1 = acc[mt][nt][rr * 2 + 1] + s_bias[cn + 1];
                float p0 = __shfl_xor_sync(0xffffffffu, v0, 1);
                float p1 = __shfl_xor_sync(0xffffffffu, v1, 1);
                float ipre, fpre, gpre, opre;
                if ((q & 1) == 0) { ipre = v0; fpre = v1; gpre = p0; opre = p1; }
                else              { ipre = p0; fpre = p1; gpre = v0; opre = v1; }

                float iv = sigmoid_fast(ipre);
                float fv = sigmoid_fast(fpre);
                float gv = tanh_fast(gpre);
                float ov = sigmoid_fast(opre);

                float oc = old_c[(size_t)b * HDIM + h];
                float nc = fmaf(fv, oc, iv * gv);
                float nh = ov * tanh_fast(nc);

                size_t idx = (size_t)b * HDIM + h;
                if ((q & 1) == 0) {
                    out[idx] = nh;
                } else {
                    if (seg1) out[(size_t)BH + idx] = nh;
                    if (seg2) out[(size_t)(2 * BH) + idx] = nc;
                }
            }
        }
    }
}

extern "C" void kernel_launch(void* const* d_in, const int* in_sizes, int n_in,
                              void* d_out, int out_size) {
    const float* incoming = (const float*)d_in[0];
    const float* old_h    = (const float*)d_in[1];
    const float* old_c    = (const float*)d_in[2];
    const float* Wi       = (const float*)d_in[3];
    const float* bi       = (const float*)d_in[4];
    const float* Wh       = (const float*)d_in[5];
    float* out = (float*)d_out;

    int a_chunks = (MDIM / 16) * (KDIM / 16) * 32;   // 4,194,304
    int w_chunks = (NDIM / 8) * (KDIM / 32) * 32;    // 1,048,576
    pack_A<<<a_chunks / 256, 256>>>(incoming, old_h);
    pack_W<<<w_chunks / 256, 256>>>(Wi, Wh);

    static int smem_set = 0;
    if (!smem_set) {
        cudaFuncSetAttribute(lstm_mma, cudaFuncAttributeMaxDynamicSharedMemorySize,
                             STAGES * STAGE_BYTES);
        smem_set = 1;
    }
    dim3 grid(NDIM / BN, MDIM / BM);   // (32, 64)
    lstm_mma<<<grid, THREADS, STAGES * STAGE_BYTES>>>(old_c, bi, out, (long long)out_size);
}

// round 6
// speedup vs baseline: 1.9313x; 1.2311x over previous
#include <cuda_runtime.h>
#include <cuda_fp16.h>
#include <cstdint>
#include <cstddef>

#define MDIM 16384
#define NDIM 4096
#define KDIM 2048
#define HDIM 1024

#define BM 128
#define BN 128
#define BK 64
#define STAGES 3
#define THREADS 256
#define NKT (KDIM / BK)              // 32

#define A_BYTES 16384                // 8 mblk x 4 ks16 x 512B
#define B_BYTES 16384                // 16 nblk x 2 k32 x 512B
#define STAGE_BYTES (A_BYTES + B_BYTES)   // 32768

// Fragment-packed operands (device globals: allowed scratch)
__device__ __half g_Apack[(size_t)MDIM * KDIM];   // 64 MB
__device__ __half g_Wpack[(size_t)NDIM * KDIM];   // 16 MB

// ---------------- helpers ----------------
__device__ __forceinline__ uint32_t cvta_s(const void* p) {
    return (uint32_t)__cvta_generic_to_shared(p);
}
__device__ __forceinline__ void cp_async16(uint32_t s, const void* g) {
    asm volatile("cp.async.cg.shared.global [%0], [%1], 16;\n" :: "r"(s), "l"(g));
}
__device__ __forceinline__ void cp_commit() { asm volatile("cp.async.commit_group;\n" ::: "memory"); }
#define CP_WAIT(n) asm volatile("cp.async.wait_group %0;\n" :: "n"(n) : "memory")

__device__ __forceinline__ void mma_f16(float* d, const uint32_t* a, const uint32_t* b) {
    asm volatile("mma.sync.aligned.m16n8k16.row.col.f32.f16.f16.f32 "
        "{%0,%1,%2,%3}, {%4,%5,%6,%7}, {%8,%9}, {%0,%1,%2,%3};\n"
        : "+f"(d[0]), "+f"(d[1]), "+f"(d[2]), "+f"(d[3])
        : "r"(a[0]), "r"(a[1]), "r"(a[2]), "r"(a[3]), "r"(b[0]), "r"(b[1]));
}
__device__ __forceinline__ float tanh_fast(float x) {
    float r; asm("tanh.approx.f32 %0, %1;\n" : "=f"(r) : "f"(x)); return r;
}
__device__ __forceinline__ float sigmoid_fast(float x) {
    return fmaf(tanh_fast(0.5f * x), 0.5f, 0.5f);
}

// ---------------- pack kernels (verified round 3) ----------------
__global__ void pack_A(const float* __restrict__ inc, const float* __restrict__ oh) {
    int idx = blockIdx.x * blockDim.x + threadIdx.x;     // one 16B chunk
    int lane = idx & 31;
    int unit = idx >> 5;
    int kblk = unit & 127;        // K/16
    int mblk = unit >> 7;
    int gid = lane >> 2, q = lane & 3;
    int m0 = mblk * 16 + gid;
    int k0 = kblk * 16 + 2 * q;
    const float* src;
    if (k0 < 1024) src = inc + (size_t)m0 * 1024 + k0;
    else           src = oh  + (size_t)m0 * 1024 + (k0 - 1024);
    float2 v0 = *(const float2*)(src);
    float2 v1 = *(const float2*)(src + 8 * 1024);
    float2 v2 = *(const float2*)(src + 8);
    float2 v3 = *(const float2*)(src + 8 * 1024 + 8);
    __half2 h[4];
    h[0] = __floats2half2_rn(v0.x, v0.y);
    h[1] = __floats2half2_rn(v1.x, v1.y);
    h[2] = __floats2half2_rn(v2.x, v2.y);
    h[3] = __floats2half2_rn(v3.x, v3.y);
    *(float4*)(g_Apack + (size_t)unit * 256 + lane * 8) = *(float4*)h;
}

__global__ void pack_W(const float* __restrict__ Wi, const float* __restrict__ Wh) {
    int idx = blockIdx.x * blockDim.x + threadIdx.x;
    int lane = idx & 31;
    int unit = idx >> 5;
    int kblk = unit & 63;         // K/32
    int nblk = unit >> 6;
    int gid = lane >> 2, q = lane & 3;
    int n = nblk * 8 + gid;
    int g = n & 3, hh = n >> 2;
    int k0 = kblk * 32 + 2 * q;
    const float* src;
    if (k0 < 1024) src = Wi + ((size_t)g * 1024 + hh) * 1024 + k0;
    else           src = Wh + ((size_t)g * 1024 + hh) * 1024 + (k0 - 1024);
    float2 v0 = *(const float2*)(src);
    float2 v1 = *(const float2*)(src + 8);
    float2 v2 = *(const float2*)(src + 16);
    float2 v3 = *(const float2*)(src + 24);
    __half2 h[4];
    h[0] = __floats2half2_rn(v0.x, v0.y);
    h[1] = __floats2half2_rn(v1.x, v1.y);
    h[2] = __floats2half2_rn(v2.x, v2.y);
    h[3] = __floats2half2_rn(v3.x, v3.y);
    *(float4*)(g_Wpack + (size_t)unit * 256 + lane * 8) = *(float4*)h;
}

// ---------------- main GEMM + fused LSTM epilogue ----------------
// 8 warps, warp tile 64x32: warp grid 2(M) x 4(N); 2 CTAs/SM
__global__ void __launch_bounds__(THREADS, 2)
lstm_mma(const float* __restrict__ old_c, const float* __restrict__ bi,
         float* __restrict__ out, long long out_size)
{
    extern __shared__ char dsm[];
    __shared__ float4 s_bias4[32];    // [h_local] -> (bi_i, bi_f, bi_g, bi_o)

    const int tid  = threadIdx.x;
    const int lane = tid & 31;
    const int warp = tid >> 5;            // 0..7
    const int wr = warp >> 2;             // 0..1 -> M (64 rows each)
    const int wc = warp & 3;              // 0..3 -> N (32 cols each)
    const int bm = blockIdx.y * BM;
    const int bn = blockIdx.x * BN;
    const int gid = lane >> 2, q = lane & 3;

    const uint32_t smem = cvta_s(dsm);

    // bias: 32 h-units of this CTA, 4 gates each (ordered by first mainloop barrier)
    if (tid < 32) {
        int hg = (bn >> 2) + tid;
        s_bias4[tid] = make_float4(bi[hg], bi[1024 + hg], bi[2048 + hg], bi[3072 + hg]);
    }

    float acc[4][4][4];
#pragma unroll
    for (int a = 0; a < 4; a++)
#pragma unroll
        for (int b = 0; b < 4; b++)
#pragma unroll
            for (int c = 0; c < 4; c++) acc[a][b][c] = 0.f;

    const size_t a_row_unit = (size_t)(bm / 16) * 128;
    const size_t b_row_unit = (size_t)(bn / 8) * 64;

    // producer: per warp 4 A units + 4 B units per ktile (1 cp.async16/lane each)
    auto produce = [&](int kt, int st) {
        uint32_t sa = smem + st * STAGE_BYTES;
        uint32_t sb = sa + A_BYTES;
#pragma unroll
        for (int i = 0; i < 4; i++) {
            int u = warp * 4 + i;              // 0..31: mblk = u>>2, ks16 = u&3
            const __half* src = g_Apack +
                (a_row_unit + (size_t)(u >> 2) * 128 + kt * 4 + (u & 3)) * 256 + lane * 8;
            cp_async16(sa + u * 512 + lane * 16, src);
        }
#pragma unroll
        for (int i = 0; i < 4; i++) {
            int u = warp * 4 + i;              // 0..31: nblk = u>>1, k32 = u&1
            const __half* src = g_Wpack +
                (b_row_unit + (size_t)(u >> 1) * 64 + kt * 2 + (u & 1)) * 256 + lane * 8;
            cp_async16(sb + u * 512 + lane * 16, src);
        }
    };

    // prologue: stages 0,1
    produce(0, 0); cp_commit();
    produce(1, 1); cp_commit();

    int st = 0;           // consume stage
    int pst = 2;          // produce stage
    for (int kt = 0; kt < NKT; kt++) {
        CP_WAIT(1);                   // group kt landed
        __syncthreads();              // stage pst free for reuse

        int nk = kt + STAGES - 1;
        if (nk < NKT) produce(nk, pst);
        cp_commit();                  // commit every iter -> wait-group math fixed

        const char* sA = dsm + st * STAGE_BYTES;
        const char* sB = sA + A_BYTES;

#pragma unroll
        for (int ks32 = 0; ks32 < 2; ks32++) {
            uint32_t bfr[4][4];
#pragma unroll
            for (int nt = 0; nt < 4; nt++)
                *(uint4*)bfr[nt] = *(const uint4*)(sB + ((wc * 4 + nt) * 2 + ks32) * 512 + lane * 16);
#pragma unroll
            for (int ki = 0; ki < 2; ki++) {
                int ks16 = ks32 * 2 + ki;
                uint32_t afr[4][4];
#pragma unroll
                for (int mt = 0; mt < 4; mt++)
                    *(uint4*)afr[mt] = *(const uint4*)(sA + (((wr * 4 + mt) * 4) + ks16) * 512 + lane * 16);
#pragma unroll
                for (int mt = 0; mt < 4; mt++)
#pragma unroll
                    for (int nt = 0; nt < 4; nt++)
                        mma_f16(acc[mt][nt], afr[mt], &bfr[nt][ki * 2]);
            }
        }
        if (++st == STAGES) st = 0;
        if (++pst == STAGES) pst = 0;
    }

    // drain all cp.async groups, then reuse stage smem for the gate buffer
    CP_WAIT(0);
    __syncthreads();

    // ---- Phase A: dump raw gate pre-activations to smem ----
    // layout: sg[(row*33 + h)*4 + gate]  (row-stride 33 float4s -> conflict-free)
    float* sg = (float*)dsm;
#pragma unroll
    for (int mt = 0; mt < 4; mt++) {
#pragma unroll
        for (int rr = 0; rr < 2; rr++) {
            int row = wr * 64 + mt * 16 + gid + rr * 8;
#pragma unroll
            for (int nt = 0; nt < 4; nt++) {
                int h = wc * 8 + nt * 2 + (q >> 1);
                // even-q lane holds gates (i,f); odd-q lane gates (g,o) of the same h
                *(float2*)(sg + (row * 33 + h) * 4 + (q & 1) * 2) =
                    make_float2(acc[mt][nt][rr * 2 + 0], acc[mt][nt][rr * 2 + 1]);
            }
        }
    }
    __syncthreads();

    // ---- Phase B: coalesced cell update + stores ----
    const long long BH = (long long)MDIM * HDIM;
    const bool seg1 = out_size >= 2 * BH;
    const bool seg2 = out_size >= 3 * BH;
    const int hbase = bn >> 2;

#pragma unroll 4
    for (int it = 0; it < 16; it++) {
        int idx = it * THREADS + tid;
        int row = idx >> 5;            // 0..127
        int h   = idx & 31;            // 0..31
        float4 ga = *(const float4*)(sg + (row * 33 + h) * 4);
        float4 bb = s_bias4[h];
        size_t gidx = (size_t)(bm + row) * HDIM + hbase + h;
        float oc = old_c[gidx];
        float iv = sigmoid_fast(ga.x + bb.x);
        float fv = sigmoid_fast(ga.y + bb.y);
        float gv = tanh_fast(ga.z + bb.z);
        float ov = sigmoid_fast(ga.w + bb.w);
        float nc = fmaf(fv, oc, iv * gv);
        float nh = ov * tanh_fast(nc);
        out[gidx] = nh;
        if (seg1) out[BH + gidx] = nh;
        if (seg2) out[2 * BH + gidx] = nc;
    }
}

extern "C" void kernel_launch(void* const* d_in, const int* in_sizes, int n_in,
                              void* d_out, int out_size) {
    const float* incoming = (const float*)d_in[0];
    const float* old_h    = (const float*)d_in[1];
    const float* old_c    = (const float*)d_in[2];
    const float* Wi       = (const float*)d_in[3];
    const float* bi       = (const float*)d_in[4];
    const float* Wh       = (const float*)d_in[5];
    float* out = (float*)d_out;

    int a_chunks = (MDIM / 16) * (KDIM / 16) * 32;   // 4,194,304
    int w_chunks = (NDIM / 8) * (KDIM / 32) * 32;    // 1,048,576
    pack_A<<<a_chunks / 256, 256>>>(incoming, old_h);
    pack_W<<<w_chunks / 256, 256>>>(Wi, Wh);

    static int smem_set = 0;
    if (!smem_set) {
        cudaFuncSetAttribute(lstm_mma, cudaFuncAttributeMaxDynamicSharedMemorySize,
                             STAGES * STAGE_BYTES);
        smem_set = 1;
    }
    dim3 grid(NDIM / BN, MDIM / BM);   // (32, 128)
    lstm_mma<<<grid, THREADS, STAGES * STAGE_BYTES>>>(old_c, bi, out, (long long)out_size);
}

// round 7
// speedup vs baseline: 2.0482x; 1.0606x over previous
#include <cuda_runtime.h>
#include <cuda_fp16.h>
#include <cstdint>
#include <cstddef>

#define MDIM 16384
#define NDIM 4096
#define KDIM 2048
#define HDIM 1024

#define BM 128
#define BN 128
#define BK 64
#define STAGES 3
#define THREADS 256
#define NKT (KDIM / BK)              // 32

#define A_BYTES 16384
#define B_BYTES 16384
#define STAGE_BYTES (A_BYTES + B_BYTES)   // 32768

// Fragment-packed operands (device globals: allowed scratch)
__device__ __half g_Apack[(size_t)MDIM * KDIM];   // 64 MB
__device__ __half g_Wpack[(size_t)NDIM * KDIM];   // 16 MB

// ---------------- helpers ----------------
__device__ __forceinline__ uint32_t cvta_s(const void* p) {
    return (uint32_t)__cvta_generic_to_shared(p);
}
__device__ __forceinline__ void cp_async16(uint32_t s, const void* g) {
    asm volatile("cp.async.cg.shared.global [%0], [%1], 16;\n" :: "r"(s), "l"(g));
}
__device__ __forceinline__ void cp_commit() { asm volatile("cp.async.commit_group;\n" ::: "memory"); }
#define CP_WAIT(n) asm volatile("cp.async.wait_group %0;\n" :: "n"(n) : "memory")

__device__ __forceinline__ void mma_f16(float* d, const uint32_t* a, const uint32_t* b) {
    asm volatile("mma.sync.aligned.m16n8k16.row.col.f32.f16.f16.f32 "
        "{%0,%1,%2,%3}, {%4,%5,%6,%7}, {%8,%9}, {%0,%1,%2,%3};\n"
        : "+f"(d[0]), "+f"(d[1]), "+f"(d[2]), "+f"(d[3])
        : "r"(a[0]), "r"(a[1]), "r"(a[2]), "r"(a[3]), "r"(b[0]), "r"(b[1]));
}
__device__ __forceinline__ float tanh_fast(float x) {
    float r; asm("tanh.approx.f32 %0, %1;\n" : "=f"(r) : "f"(x)); return r;
}
__device__ __forceinline__ float sigmoid_fast(float x) {
    return fmaf(tanh_fast(0.5f * x), 0.5f, 0.5f);
}

// ---------------- merged pack kernel ----------------
// blocks [0, aBlocks): A chunks; blocks [aBlocks, aBlocks+wBlocks): W chunks
__global__ void pack_AW(const float* __restrict__ inc, const float* __restrict__ oh,
                        const float* __restrict__ Wi, const float* __restrict__ Wh,
                        int aBlocks) {
    if ((int)blockIdx.x < aBlocks) {
        int idx = blockIdx.x * blockDim.x + threadIdx.x;
        int lane = idx & 31;
        int unit = idx >> 5;
        int kblk = unit & 127;
        int mblk = unit >> 7;
        int gid = lane >> 2, q = lane & 3;
        int m0 = mblk * 16 + gid;
        int k0 = kblk * 16 + 2 * q;
        const float* src;
        if (k0 < 1024) src = inc + (size_t)m0 * 1024 + k0;
        else           src = oh  + (size_t)m0 * 1024 + (k0 - 1024);
        float2 v0 = *(const float2*)(src);
        float2 v1 = *(const float2*)(src + 8 * 1024);
        float2 v2 = *(const float2*)(src + 8);
        float2 v3 = *(const float2*)(src + 8 * 1024 + 8);
        __half2 h[4];
        h[0] = __floats2half2_rn(v0.x, v0.y);
        h[1] = __floats2half2_rn(v1.x, v1.y);
        h[2] = __floats2half2_rn(v2.x, v2.y);
        h[3] = __floats2half2_rn(v3.x, v3.y);
        *(float4*)(g_Apack + (size_t)unit * 256 + lane * 8) = *(float4*)h;
    } else {
        int idx = (blockIdx.x - aBlocks) * blockDim.x + threadIdx.x;
        int lane = idx & 31;
        int unit = idx >> 5;
        int kblk = unit & 63;
        int nblk = unit >> 6;
        int gid = lane >> 2, q = lane & 3;
        int n = nblk * 8 + gid;
        int g = n & 3, hh = n >> 2;
        int k0 = kblk * 32 + 2 * q;
        const float* src;
        if (k0 < 1024) src = Wi + ((size_t)g * 1024 + hh) * 1024 + k0;
        else           src = Wh + ((size_t)g * 1024 + hh) * 1024 + (k0 - 1024);
        float2 v0 = *(const float2*)(src);
        float2 v1 = *(const float2*)(src + 8);
        float2 v2 = *(const float2*)(src + 16);
        float2 v3 = *(const float2*)(src + 24);
        __half2 h[4];
        h[0] = __floats2half2_rn(v0.x, v0.y);
        h[1] = __floats2half2_rn(v1.x, v1.y);
        h[2] = __floats2half2_rn(v2.x, v2.y);
        h[3] = __floats2half2_rn(v3.x, v3.y);
        *(float4*)(g_Wpack + (size_t)unit * 256 + lane * 8) = *(float4*)h;
    }
}

// ---------------- main GEMM + fused LSTM epilogue ----------------
// 8 warps, warp tile 64x32: warp grid 2(M) x 4(N); 2 CTAs/SM
__global__ void __launch_bounds__(THREADS, 2)
lstm_mma(const float* __restrict__ old_c, const float* __restrict__ bi,
         float* __restrict__ out, long long out_size)
{
    extern __shared__ char dsm[];
    __shared__ float4 s_bias4[32];

    const int tid  = threadIdx.x;
    const int lane = tid & 31;
    const int warp = tid >> 5;            // 0..7
    const int wr = warp >> 2;             // 0..1 -> M
    const int wc = warp & 3;              // 0..3 -> N
    const int bm = blockIdx.y * BM;
    const int bn = blockIdx.x * BN;
    const int gid = lane >> 2, q = lane & 3;

    const uint32_t smem = cvta_s(dsm);

    if (tid < 32) {
        int hg = (bn >> 2) + tid;
        s_bias4[tid] = make_float4(bi[hg], bi[1024 + hg], bi[2048 + hg], bi[3072 + hg]);
    }

    float acc[4][4][4];
#pragma unroll
    for (int a = 0; a < 4; a++)
#pragma unroll
        for (int b = 0; b < 4; b++)
#pragma unroll
            for (int c = 0; c < 4; c++) acc[a][b][c] = 0.f;

    const size_t a_row_unit = (size_t)(bm / 16) * 128;
    const size_t b_row_unit = (size_t)(bn / 8) * 64;

    auto produce = [&](int kt, int st) {
        uint32_t sa = smem + st * STAGE_BYTES;
        uint32_t sb = sa + A_BYTES;
#pragma unroll
        for (int i = 0; i < 4; i++) {
            int u = warp * 4 + i;
            const __half* src = g_Apack +
                (a_row_unit + (size_t)(u >> 2) * 128 + kt * 4 + (u & 3)) * 256 + lane * 8;
            cp_async16(sa + u * 512 + lane * 16, src);
        }
#pragma unroll
        for (int i = 0; i < 4; i++) {
            int u = warp * 4 + i;
            const __half* src = g_Wpack +
                (b_row_unit + (size_t)(u >> 1) * 64 + kt * 2 + (u & 1)) * 256 + lane * 8;
            cp_async16(sb + u * 512 + lane * 16, src);
        }
    };

    auto consume = [&](int st) {
        const char* sA = dsm + st * STAGE_BYTES;
        const char* sB = sA + A_BYTES;
#pragma unroll
        for (int ks32 = 0; ks32 < 2; ks32++) {
            uint32_t bfr[4][4];
#pragma unroll
            for (int nt = 0; nt < 4; nt++)
                *(uint4*)bfr[nt] = *(const uint4*)(sB + ((wc * 4 + nt) * 2 + ks32) * 512 + lane * 16);
#pragma unroll
            for (int ki = 0; ki < 2; ki++) {
                int ks16 = ks32 * 2 + ki;
                uint32_t afr[4][4];
#pragma unroll
                for (int mt = 0; mt < 4; mt++)
                    *(uint4*)afr[mt] = *(const uint4*)(sA + ((wr * 4 + mt) * 4 + ks16) * 512 + lane * 16);
#pragma unroll
                for (int mt = 0; mt < 4; mt++)
#pragma unroll
                    for (int nt = 0; nt < 4; nt++)
                        mma_f16(acc[mt][nt], afr[mt], &bfr[nt][ki * 2]);
            }
        }
    };

    // prologue: stages 0,1
    produce(0, 0); cp_commit();
    produce(1, 1); cp_commit();

    // unroll-3 mainloop: stage indices are compile-time constants per position.
    // iter kt consumes stage kt%3, produces kt+2 into stage (kt+2)%3.
#pragma unroll 1
    for (int kt = 0; kt < 30; kt += 3) {
        CP_WAIT(1); __syncthreads();
        produce(kt + 2, 2); cp_commit();
        consume(0);

        CP_WAIT(1); __syncthreads();
        produce(kt + 3, 0); cp_commit();
        consume(1);

        CP_WAIT(1); __syncthreads();
        if (kt + 4 < NKT) produce(kt + 4, 1);
        cp_commit();
        consume(2);
    }
    // tail: kt = 30 (stage 0), kt = 31 (stage 1); nothing left to produce
    CP_WAIT(1); __syncthreads();
    cp_commit();
    consume(0);
    CP_WAIT(0); __syncthreads();
    consume(1);

    __syncthreads();

    // ---- Phase A: dump raw gate pre-activations to smem ----
    float* sg = (float*)dsm;
#pragma unroll
    for (int mt = 0; mt < 4; mt++) {
#pragma unroll
        for (int rr = 0; rr < 2; rr++) {
            int row = wr * 64 + mt * 16 + gid + rr * 8;
#pragma unroll
            for (int nt = 0; nt < 4; nt++) {
                int h = wc * 8 + nt * 2 + (q >> 1);
                *(float2*)(sg + (row * 33 + h) * 4 + (q & 1) * 2) =
                    make_float2(acc[mt][nt][rr * 2 + 0], acc[mt][nt][rr * 2 + 1]);
            }
        }
    }
    __syncthreads();

    // ---- Phase B: coalesced cell update + streaming stores ----
    const long long BH = (long long)MDIM * HDIM;
    const bool seg1 = out_size >= 2 * BH;
    const bool seg2 = out_size >= 3 * BH;
    const int hbase = bn >> 2;

#pragma unroll 4
    for (int it = 0; it < 16; it++) {
        int idx = it * THREADS + tid;
        int row = idx >> 5;
        int h   = idx & 31;
        float4 ga = *(const float4*)(sg + (row * 33 + h) * 4);
        float4 bb = s_bias4[h];
        size_t gidx = (size_t)(bm + row) * HDIM + hbase + h;
        float oc = __ldcs(old_c + gidx);
        float iv = sigmoid_fast(ga.x + bb.x);
        float fv = sigmoid_fast(ga.y + bb.y);
        float gv = tanh_fast(ga.z + bb.z);
        float ov = sigmoid_fast(ga.w + bb.w);
        float nc = fmaf(fv, oc, iv * gv);
        float nh = ov * tanh_fast(nc);
        __stcs(out + gidx, nh);
        if (seg1) __stcs(out + BH + gidx, nh);
        if (seg2) __stcs(out + 2 * BH + gidx, nc);
    }
}

extern "C" void kernel_launch(void* const* d_in, const int* in_sizes, int n_in,
                              void* d_out, int out_size) {
    const float* incoming = (const float*)d_in[0];
    const float* old_h    = (const float*)d_in[1];
    const float* old_c    = (const float*)d_in[2];
    const float* Wi       = (const float*)d_in[3];
    const float* bi       = (const float*)d_in[4];
    const float* Wh       = (const float*)d_in[5];
    float* out = (float*)d_out;

    int aBlocks = (MDIM / 16) * (KDIM / 16) * 32 / 256;   // 16384
    int wBlocks = (NDIM / 8) * (KDIM / 32) * 32 / 256;    // 4096
    pack_AW<<<aBlocks + wBlocks, 256>>>(incoming, old_h, Wi, Wh, aBlocks);

    static int smem_set = 0;
    if (!smem_set) {
        cudaFuncSetAttribute(lstm_mma, cudaFuncAttributeMaxDynamicSharedMemorySize,
                             STAGES * STAGE_BYTES);
        smem_set = 1;
    }
    dim3 grid(NDIM / BN, MDIM / BM);   // (32, 128)
    lstm_mma<<<grid, THREADS, STAGES * STAGE_BYTES>>>(old_c, bi, out, (long long)out_size);
}